// round 10
// baseline (speedup 1.0000x reference)
#include <cuda_runtime.h>

// Problem constants (fixed by reference setup_inputs)
#define BB 128
#define SS 256
#define HH 768
#define KK 64
#define NROWS (BB * SS)     // 32768
#define V4_PER_ROW (HH / 4) // 192
#define TPB (2 * V4_PER_ROW) // 384: two rows per block
#define NBLK (NROWS / 2)     // 16384

// Two consecutive rows per block (same batch: SS is even), 384 threads,
// one float4 per thread. Membership for the two rows runs IN PARALLEL on
// warps 0 and 1 (3x int2 L2-hit loads + 3 ballots each); lane 0 of each
// folds the weights into (m0,m1,m2,skip) in smem. One __syncthreads, then
// t<192 streams row0 and t>=192 streams row1 with broadcast LDS multipliers.
//
// Read-skip (committed): rows with s!=0 && !dep && !dpd are all-zero in all
// three outputs (~60%) -> store zeros, skip the 3 KB input read.
// Streaming hints (committed): __ldcs read-once input, __stcs write-once
// outputs.
//
// Validity: indices lie in [0, S) and target = s-1 <= S-2, so idx == S-1
// never matches -- identical to the reference's (idx + 1 < S) check.
__global__ __launch_bounds__(TPB) void fused_kernel(
    const float4* __restrict__ in,
    const int*    __restrict__ depend,
    const int*    __restrict__ depended,
    const int*    __restrict__ noconn,
    const float*  __restrict__ dep_w,
    const float*  __restrict__ dpd_w,
    float4*       __restrict__ out)
{
    const unsigned row0 = blockIdx.x * 2u;
    const unsigned t    = threadIdx.x;

    __shared__ float sh_m[2][3];
    __shared__ int   sh_skip[2];

    // membership: warp 0 -> row0, warp 1 -> row0+1 (independent, parallel)
    if (t < 64) {
        const unsigned w    = t >> 5;          // 0 or 1: which row
        const unsigned lane = t & 31;
        const unsigned row  = row0 + w;
        const int b      = row >> 8;           // row / SS
        const int s      = row & (SS - 1);     // row % SS
        const int target = s - 1;              // s=0 -> -1, never matches

        const float w1 = __ldg(&dep_w[b]);
        const float w2 = __ldg(&dpd_w[b]);

        const int2 d2 = __ldg(&((const int2*)(depend   + b * KK))[lane]);
        const int2 e2 = __ldg(&((const int2*)(depended + b * KK))[lane]);
        const int2 n2 = __ldg(&((const int2*)(noconn   + b * KK))[lane]);

        const bool dep = __ballot_sync(0xffffffffu,
                            (d2.x == target) | (d2.y == target)) != 0;
        const bool dpd = __ballot_sync(0xffffffffu,
                            (e2.x == target) | (e2.y == target)) != 0;
        const bool noc = __ballot_sync(0xffffffffu,
                            (n2.x == target) | (n2.y == target)) != 0;

        if (lane == 0) {
            const bool p0 = (s == 0);
            sh_m[w][0] = (p0 || dep) ? 1.0f : 0.0f;
            sh_m[w][1] = (p0 || dpd) ? 1.0f : 0.0f;
            float m2 = dep ? w1 : 0.0f;
            if (dpd) m2 = w2;
            if (noc) m2 = 0.0f;
            if (p0)  m2 = 1.0f;
            sh_m[w][2] = m2;
            sh_skip[w] = (!p0 && !dep && !dpd) ? 1 : 0;
        }
    }
    __syncthreads();

    const unsigned half = t / V4_PER_ROW;        // 0 or 1: which row
    const unsigned tt   = t - half * V4_PER_ROW; // 0..191
    const unsigned idx  = (row0 + half) * V4_PER_ROW + tt;
    const unsigned N4   = NROWS * V4_PER_ROW;

    if (sh_skip[half]) {
        // all three outputs zero for this row: no input read needed
        const float4 z = make_float4(0.0f, 0.0f, 0.0f, 0.0f);
        __stcs(&out[idx],           z);
        __stcs(&out[N4 + idx],      z);
        __stcs(&out[2u * N4 + idx], z);
        return;
    }

    const float m0 = sh_m[half][0];
    const float m1 = sh_m[half][1];
    const float m2 = sh_m[half][2];

    const float4 v = __ldcs(&in[idx]);   // read-once: evict-first

    float4 a, bb, c;
    a.x  = v.x * m0; a.y  = v.y * m0; a.z  = v.z * m0; a.w  = v.w * m0;
    bb.x = v.x * m1; bb.y = v.y * m1; bb.z = v.z * m1; bb.w = v.w * m1;
    c.x  = v.x * m2; c.y  = v.y * m2; c.z  = v.z * m2; c.w  = v.w * m2;

    __stcs(&out[idx],           a);      // write-once: evict-first
    __stcs(&out[N4 + idx],      bb);
    __stcs(&out[2u * N4 + idx], c);
}

extern "C" void kernel_launch(void* const* d_in, const int* in_sizes, int n_in,
                              void* d_out, int out_size) {
    const float* bert     = (const float*)d_in[0];
    const int*   depend   = (const int*)d_in[1];
    const int*   depended = (const int*)d_in[2];
    const int*   noconn   = (const int*)d_in[3];
    const float* dep_w    = (const float*)d_in[4];
    const float* dpd_w    = (const float*)d_in[5];
    float*       out      = (float*)d_out;

    fused_kernel<<<NBLK, TPB>>>((const float4*)bert, depend, depended,
                                noconn, dep_w, dpd_w, (float4*)out);
}